// round 3
// baseline (speedup 1.0000x reference)
#include <cuda_runtime.h>
#include <stdint.h>

#define BATCH 2048
#define KTOP  32
#define DDIM  768
#define DICT  24576
#define CONN  64

#define MAXPAIRS (BATCH * KTOP * KTOP)

__device__ float    g_bias[DICT];
__device__ unsigned g_npairs;
__device__ int      g_needed[DICT];
__device__ float    g_ut[DICT * DDIM];   // transposed up_decoder_w (needed rows only)
// pair record: x = out position (b*K+i), y = down dict idx, z = up dict idx,
//              w = float bits of (mult * up_val)
__device__ uint4    g_pairs[MAXPAIRS];

// ---------------------------------------------------------------------------
// Kernel 1: bias = up_encoder_w @ b_dec.  2 rows per warp (MLP=12).
// Also zeroes g_npairs and g_needed.
// ---------------------------------------------------------------------------
__global__ __launch_bounds__(256) void bias_kernel(
    const float* __restrict__ up_encoder_w,   // [DICT, D]
    const float* __restrict__ b_dec)          // [D]
{
    if (blockIdx.x == 0 && threadIdx.x == 0) g_npairs = 0;
    if (blockIdx.x < DICT / 256) g_needed[blockIdx.x * 256 + threadIdx.x] = 0;

    __shared__ float s_b[DDIM];
    for (int i = threadIdx.x; i < DDIM; i += blockDim.x) s_b[i] = b_dec[i];
    __syncthreads();

    int warp = threadIdx.x >> 5;
    int lane = threadIdx.x & 31;
    int row0 = (blockIdx.x * 8 + warp) * 2;      // 16 rows per block

    const float4* w0 = reinterpret_cast<const float4*>(up_encoder_w + (size_t)row0 * DDIM);
    const float4* w1 = reinterpret_cast<const float4*>(up_encoder_w + (size_t)(row0 + 1) * DDIM);
    const float4* bb = reinterpret_cast<const float4*>(s_b);
    float a0 = 0.f, a1 = 0.f;
#pragma unroll
    for (int k = 0; k < DDIM / 128; k++) {       // 6 iterations, 12 indep loads
        float4 b = bb[lane + 32 * k];
        float4 v0 = w0[lane + 32 * k];
        float4 v1 = w1[lane + 32 * k];
        a0 += v0.x * b.x + v0.y * b.y + v0.z * b.z + v0.w * b.w;
        a1 += v1.x * b.x + v1.y * b.y + v1.z * b.z + v1.w * b.w;
    }
#pragma unroll
    for (int o = 16; o > 0; o >>= 1) {
        a0 += __shfl_xor_sync(0xffffffffu, a0, o);
        a1 += __shfl_xor_sync(0xffffffffu, a1, o);
    }
    if (lane == 0) { g_bias[row0] = a0; g_bias[row0 + 1] = a1; }
}

// ---------------------------------------------------------------------------
// Kernel 2: matching. One block per batch element. Emits pair records, marks
// needed columns, writes bias base into out.
// ---------------------------------------------------------------------------
#define HSZ 64

__global__ __launch_bounds__(128) void match_kernel(
    const float* __restrict__ up_vals,        // [B, K]
    const int*   __restrict__ up_indices,     // [B, K]
    const int*   __restrict__ down_indices,   // [B, K]
    const int*   __restrict__ connections,    // [DICT, C]
    float*       __restrict__ out)            // [B, K]
{
    __shared__ int   s_up_idx[KTOP];
    __shared__ float s_up_val[KTOP];
    __shared__ int   s_down_idx[KTOP];
    __shared__ int   s_hkey[HSZ];
    __shared__ int   s_hj[HSZ];
    __shared__ int   s_mult[KTOP * KTOP];

    const int b = blockIdx.x;
    const int t = threadIdx.x;

    if (t < KTOP) {
        s_up_idx[t]   = up_indices[b * KTOP + t];
        s_up_val[t]   = up_vals[b * KTOP + t];
        s_down_idx[t] = down_indices[b * KTOP + t];
    }
    if (t < HSZ) s_hkey[t] = -1;
    for (int e = t; e < KTOP * KTOP; e += blockDim.x) s_mult[e] = 0;
    __syncthreads();

    // Hash table of up indices (duplicates get their own probe slots).
    if (t < KTOP) {
        int key = s_up_idx[t];
        unsigned p = ((unsigned)key * 2654435761u) >> 26;
        while (true) {
            int old = atomicCAS(&s_hkey[p & (HSZ - 1)], -1, key);
            if (old == -1) { s_hj[p & (HSZ - 1)] = t; break; }
            p++;
        }
    }
    __syncthreads();

    // Stream connection slots through the hash table.
    for (int item = t; item < KTOP * (CONN / 4); item += blockDim.x) {
        int i = item >> 4;
        int q = item & 15;
        int di = s_down_idx[i];
        int4 a = reinterpret_cast<const int4*>(connections + (size_t)di * CONN)[q];
        int av[4] = {a.x, a.y, a.z, a.w};
#pragma unroll
        for (int s = 0; s < 4; s++) {
            int v = av[s];
            if (v < 0) continue;
            unsigned p = ((unsigned)v * 2654435761u) >> 26;
            while (true) {
                int k = s_hkey[p & (HSZ - 1)];
                if (k == -1) break;
                if (k == v) atomicAdd(&s_mult[i * KTOP + s_hj[p & (HSZ - 1)]], 1);
                p++;
            }
        }
    }
    __syncthreads();

    // Emit nonzero pairs, mark needed up-columns.
    for (int e = t; e < KTOP * KTOP; e += blockDim.x) {
        int m = s_mult[e];
        if (m != 0) {
            int i = e >> 5;
            int j = e & 31;
            int uj = s_up_idx[j];
            g_needed[uj] = 1;
            unsigned p = atomicAdd(&g_npairs, 1u);
            uint4 rec;
            rec.x = (unsigned)(b * KTOP + i);
            rec.y = (unsigned)s_down_idx[i];
            rec.z = (unsigned)uj;
            rec.w = __float_as_uint((float)m * s_up_val[j]);
            g_pairs[p] = rec;
        }
    }

    if (t < KTOP)
        out[b * KTOP + t] = g_bias[s_up_idx[t]];
}

// ---------------------------------------------------------------------------
// Kernel 3: selective transpose of up_decoder_w [D, DICT] -> g_ut [DICT, D].
// Coalesced reads of full rows; writes only rows marked needed.
// ---------------------------------------------------------------------------
__global__ __launch_bounds__(256) void transpose_kernel(
    const float* __restrict__ up_decoder_w)   // [D, DICT]
{
    __shared__ float s[32][33];

    const int ftile = blockIdx.x % (DICT / 32);
    const int dtile = blockIdx.x / (DICT / 32);
    const int f0 = ftile * 32;
    const int d0 = dtile * 32;
    const int tx = threadIdx.x & 31;
    const int ty = threadIdx.x >> 5;

    // Early out if no column in this f-tile is needed.
    bool any;
    {
        int flag = (threadIdx.x < 32) ? g_needed[f0 + threadIdx.x] : 0;
        any = __syncthreads_or(flag);
    }
    if (!any) return;

#pragma unroll
    for (int r = 0; r < 4; r++) {
        int d = d0 + ty + 8 * r;
        s[ty + 8 * r][tx] = up_decoder_w[(size_t)d * DICT + f0 + tx];
    }
    __syncthreads();

#pragma unroll
    for (int r = 0; r < 4; r++) {
        int f = f0 + ty + 8 * r;
        if (g_needed[f])
            g_ut[(size_t)f * DDIM + d0 + tx] = s[tx][ty + 8 * r];
    }
}

// ---------------------------------------------------------------------------
// Kernel 4: one warp per pair; both operands now coalesced float4 rows.
// ---------------------------------------------------------------------------
__global__ __launch_bounds__(256) void pair_kernel(
    const float* __restrict__ down_encoder_w, // [DICT, D]
    float*       __restrict__ out)            // [B, K]
{
    const unsigned np = g_npairs;
    const int lane = threadIdx.x & 31;
    const unsigned warp_id = (blockIdx.x * (blockDim.x >> 5)) + (threadIdx.x >> 5);
    const unsigned nwarps  = gridDim.x * (blockDim.x >> 5);

    for (unsigned p = warp_id; p < np; p += nwarps) {
        uint4 rec = g_pairs[p];
        const float4* a = reinterpret_cast<const float4*>(g_ut + (size_t)rec.z * DDIM);
        const float4* d = reinterpret_cast<const float4*>(down_encoder_w + (size_t)rec.y * DDIM);
        float acc = 0.f;
#pragma unroll
        for (int k = 0; k < DDIM / 128; k++) {       // 6 iters, 12 indep loads
            float4 va = a[lane + 32 * k];
            float4 vd = d[lane + 32 * k];
            acc += va.x * vd.x + va.y * vd.y + va.z * vd.z + va.w * vd.w;
        }
#pragma unroll
        for (int o = 16; o > 0; o >>= 1) acc += __shfl_xor_sync(0xffffffffu, acc, o);
        if (lane == 0)
            atomicAdd(&out[rec.x], acc * __uint_as_float(rec.w));
    }
}

// ---------------------------------------------------------------------------
extern "C" void kernel_launch(void* const* d_in, const int* in_sizes, int n_in,
                              void* d_out, int out_size)
{
    const float* up_vals        = (const float*)d_in[0];
    const float* up_decoder_w   = (const float*)d_in[1];
    const float* down_encoder_w = (const float*)d_in[2];
    const float* up_encoder_w   = (const float*)d_in[3];
    const float* b_dec          = (const float*)d_in[4];
    const int*   up_indices     = (const int*)d_in[5];
    const int*   down_indices   = (const int*)d_in[6];
    const int*   connections    = (const int*)d_in[7];
    float*       out            = (float*)d_out;

    bias_kernel<<<DICT / 16, 256>>>(up_encoder_w, b_dec);
    match_kernel<<<BATCH, 128>>>(up_vals, up_indices, down_indices,
                                 connections, out);
    transpose_kernel<<<(DDIM / 32) * (DICT / 32), 256>>>(up_decoder_w);
    pair_kernel<<<1024, 256>>>(down_encoder_w, out);
}

// round 4
// speedup vs baseline: 1.0742x; 1.0742x over previous
#include <cuda_runtime.h>
#include <stdint.h>

#define BATCH 2048
#define KTOP  32
#define DDIM  768
#define DICT  24576
#define CONN  64

#define FT    64                 // up-feature tile width
#define NFT   (DICT / FT)        // 384 tiles
#define DH    384                // d-half size (2 halves of DDIM)
#define CAP   512                // max pair records per tile bucket
#define SROW  (FT + 1)           // padded smem row stride (65)

__device__ float    g_bias[DICT];
__device__ unsigned g_bcnt[NFT];
// pair record: x = out position (b*K+i), y = down dict idx, z = up dict idx,
//              w = float bits of (mult * up_val)
__device__ uint4    g_bpairs[NFT * CAP];

// ---------------------------------------------------------------------------
// Kernel 1: bias = up_encoder_w @ b_dec. 4 rows per warp (MLP 24).
// Also zeroes the bucket counters.
// ---------------------------------------------------------------------------
__global__ __launch_bounds__(256) void bias_kernel(
    const float* __restrict__ up_encoder_w,   // [DICT, D]
    const float* __restrict__ b_dec)          // [D]
{
    int gid = blockIdx.x * 256 + threadIdx.x;
    if (gid < NFT) g_bcnt[gid] = 0;

    __shared__ float s_b[DDIM];
    for (int i = threadIdx.x; i < DDIM; i += blockDim.x) s_b[i] = b_dec[i];
    __syncthreads();

    int warp = threadIdx.x >> 5;
    int lane = threadIdx.x & 31;
    int row0 = (blockIdx.x * 8 + warp) * 4;      // 32 rows per block

    const float4* w  = reinterpret_cast<const float4*>(up_encoder_w + (size_t)row0 * DDIM);
    const float4* bb = reinterpret_cast<const float4*>(s_b);
    const int RS = DDIM / 4;                     // float4 row stride (192)
    float a0 = 0.f, a1 = 0.f, a2 = 0.f, a3 = 0.f;
#pragma unroll
    for (int k = 0; k < DDIM / 128; k++) {       // 6 iters, 24 indep loads
        int c = lane + 32 * k;
        float4 b  = bb[c];
        float4 v0 = w[0 * RS + c];
        float4 v1 = w[1 * RS + c];
        float4 v2 = w[2 * RS + c];
        float4 v3 = w[3 * RS + c];
        a0 += v0.x * b.x + v0.y * b.y + v0.z * b.z + v0.w * b.w;
        a1 += v1.x * b.x + v1.y * b.y + v1.z * b.z + v1.w * b.w;
        a2 += v2.x * b.x + v2.y * b.y + v2.z * b.z + v2.w * b.w;
        a3 += v3.x * b.x + v3.y * b.y + v3.z * b.z + v3.w * b.w;
    }
#pragma unroll
    for (int o = 16; o > 0; o >>= 1) {
        a0 += __shfl_xor_sync(0xffffffffu, a0, o);
        a1 += __shfl_xor_sync(0xffffffffu, a1, o);
        a2 += __shfl_xor_sync(0xffffffffu, a2, o);
        a3 += __shfl_xor_sync(0xffffffffu, a3, o);
    }
    if (lane == 0) {
        g_bias[row0 + 0] = a0;
        g_bias[row0 + 1] = a1;
        g_bias[row0 + 2] = a2;
        g_bias[row0 + 3] = a3;
    }
}

// ---------------------------------------------------------------------------
// Kernel 2: matching. One block per batch element. Emits pair records into
// per-f-tile buckets; zeroes its slice of out.
// ---------------------------------------------------------------------------
#define HSZ 64

__global__ __launch_bounds__(128) void match_kernel(
    const float* __restrict__ up_vals,        // [B, K]
    const int*   __restrict__ up_indices,     // [B, K]
    const int*   __restrict__ down_indices,   // [B, K]
    const int*   __restrict__ connections,    // [DICT, C]
    float*       __restrict__ out)            // [B, K]
{
    __shared__ int   s_up_idx[KTOP];
    __shared__ float s_up_val[KTOP];
    __shared__ int   s_down_idx[KTOP];
    __shared__ int   s_hkey[HSZ];
    __shared__ int   s_hj[HSZ];
    __shared__ int   s_mult[KTOP * KTOP];

    const int b = blockIdx.x;
    const int t = threadIdx.x;

    if (t < KTOP) {
        s_up_idx[t]   = up_indices[b * KTOP + t];
        s_up_val[t]   = up_vals[b * KTOP + t];
        s_down_idx[t] = down_indices[b * KTOP + t];
        out[b * KTOP + t] = 0.f;                 // base; all adds are atomic
    }
    if (t < HSZ) s_hkey[t] = -1;
    for (int e = t; e < KTOP * KTOP; e += blockDim.x) s_mult[e] = 0;
    __syncthreads();

    // Hash table of up indices (duplicates each get their own probe slot).
    if (t < KTOP) {
        int key = s_up_idx[t];
        unsigned p = ((unsigned)key * 2654435761u) >> 26;
        while (true) {
            int old = atomicCAS(&s_hkey[p & (HSZ - 1)], -1, key);
            if (old == -1) { s_hj[p & (HSZ - 1)] = t; break; }
            p++;
        }
    }
    __syncthreads();

    // Stream connection slots through the hash table.
    for (int item = t; item < KTOP * (CONN / 4); item += blockDim.x) {
        int i = item >> 4;
        int q = item & 15;
        int di = s_down_idx[i];
        int4 a = reinterpret_cast<const int4*>(connections + (size_t)di * CONN)[q];
        int av[4] = {a.x, a.y, a.z, a.w};
#pragma unroll
        for (int s = 0; s < 4; s++) {
            int v = av[s];
            if (v < 0) continue;
            unsigned p = ((unsigned)v * 2654435761u) >> 26;
            while (true) {
                int k = s_hkey[p & (HSZ - 1)];
                if (k == -1) break;
                if (k == v) atomicAdd(&s_mult[i * KTOP + s_hj[p & (HSZ - 1)]], 1);
                p++;
            }
        }
    }
    __syncthreads();

    // Emit nonzero pairs into per-tile buckets.
    for (int e = t; e < KTOP * KTOP; e += blockDim.x) {
        int m = s_mult[e];
        if (m != 0) {
            int i = e >> 5;
            int j = e & 31;
            int uj = s_up_idx[j];
            int bucket = uj >> 6;                // uj / FT
            unsigned pos = atomicAdd(&g_bcnt[bucket], 1u);
            if (pos < CAP) {
                uint4 rec;
                rec.x = (unsigned)(b * KTOP + i);
                rec.y = (unsigned)s_down_idx[i];
                rec.z = (unsigned)uj;
                rec.w = __float_as_uint((float)m * s_up_val[j]);
                g_bpairs[bucket * CAP + pos] = rec;
            }
        }
    }
}

// ---------------------------------------------------------------------------
// Kernel 3: fused dot. Blocks [0, 2*NFT): one per (f-tile, d-half) — load the
// 384x64 slab of up_decoder_w coalesced into smem, then each bucket pair does
// a smem-column x down-row dot, atomicAdd into out.
// Blocks [2*NFT, ...): scatter-add the bias base g_bias[up_indices[i]].
// ---------------------------------------------------------------------------
__global__ __launch_bounds__(256) void fused_kernel(
    const float* __restrict__ up_decoder_w,   // [D, DICT]
    const float* __restrict__ down_encoder_w, // [DICT, D]
    const int*   __restrict__ up_indices,     // [B*K] flat
    float*       __restrict__ out)            // [B*K]
{
    extern __shared__ float s[];               // [DH][SROW]

    const int t = threadIdx.x;

    if (blockIdx.x >= 2 * NFT) {
        // bias base scatter
        int i = (blockIdx.x - 2 * NFT) * 256 + t;
        atomicAdd(&out[i], g_bias[up_indices[i]]);
        return;
    }

    const int tile = blockIdx.x >> 1;
    const int half = blockIdx.x & 1;
    const unsigned cnt_raw = g_bcnt[tile];
    const int cnt = (int)(cnt_raw < CAP ? cnt_raw : CAP);
    if (cnt == 0) return;

    const int f0 = tile * FT;
    const int d0 = half * DH;

    // Load slab: DH rows x FT cols = 6144 float4 / 256 threads = 24 each.
    const float4* src = reinterpret_cast<const float4*>(
        up_decoder_w + (size_t)d0 * DICT + f0);
    const int RS4 = DICT / 4;                  // float4 row stride
#pragma unroll
    for (int it = 0; it < (DH * FT / 4) / 256; it++) {
        int idx = t + 256 * it;
        int row = idx >> 4;                    // / (FT/4)
        int c4  = idx & 15;
        float4 v = src[(size_t)row * RS4 + c4];
        float* dst = &s[row * SROW + c4 * 4];
        dst[0] = v.x; dst[1] = v.y; dst[2] = v.z; dst[3] = v.w;
    }
    __syncthreads();

    const int warp = t >> 5;
    const int lane = t & 31;
    for (int p = warp; p < cnt; p += 8) {
        uint4 rec = g_bpairs[tile * CAP + p];
        const int fl = (int)rec.z - f0;
        const float* drow = down_encoder_w + (size_t)rec.y * DDIM + d0;
        float acc = 0.f;
#pragma unroll
        for (int m = 0; m < DH / 32; m++) {    // 12 iters
            int dd = lane + 32 * m;
            acc += s[dd * SROW + fl] * drow[dd];
        }
#pragma unroll
        for (int o = 16; o > 0; o >>= 1) acc += __shfl_xor_sync(0xffffffffu, acc, o);
        if (lane == 0)
            atomicAdd(&out[rec.x], acc * __uint_as_float(rec.w));
    }
}

// ---------------------------------------------------------------------------
extern "C" void kernel_launch(void* const* d_in, const int* in_sizes, int n_in,
                              void* d_out, int out_size)
{
    const float* up_vals        = (const float*)d_in[0];
    const float* up_decoder_w   = (const float*)d_in[1];
    const float* down_encoder_w = (const float*)d_in[2];
    const float* up_encoder_w   = (const float*)d_in[3];
    const float* b_dec          = (const float*)d_in[4];
    const int*   up_indices     = (const int*)d_in[5];
    const int*   down_indices   = (const int*)d_in[6];
    const int*   connections    = (const int*)d_in[7];
    float*       out            = (float*)d_out;

    const int smem = DH * SROW * sizeof(float);  // 99,840 B
    static bool attr_set = false;
    if (!attr_set) {
        cudaFuncSetAttribute(fused_kernel,
                             cudaFuncAttributeMaxDynamicSharedMemorySize, smem);
        attr_set = true;
    }

    bias_kernel<<<DICT / 32, 256>>>(up_encoder_w, b_dec);
    match_kernel<<<BATCH, 128>>>(up_vals, up_indices, down_indices,
                                 connections, out);
    fused_kernel<<<2 * NFT + (BATCH * KTOP) / 256, 256, smem>>>(
        up_decoder_w, down_encoder_w, up_indices, out);
}

// round 5
// speedup vs baseline: 1.6501x; 1.5361x over previous
#include <cuda_runtime.h>
#include <stdint.h>

#define BATCH 2048
#define KTOP  32
#define DDIM  768
#define DICT  24576
#define CONN  64

#define FT    64                 // up-feature tile width
#define NFT   (DICT / FT)        // 384 tiles
#define DH    192                // d-slice size (4 slices of DDIM)
#define NSL   (DDIM / DH)        // 4
#define CAP   512                // max pair records per tile bucket
#define SROW  (FT + 1)           // padded smem row stride (65, odd => conflict-free cols)

__device__ float    g_bias[DICT];
__device__ unsigned g_bcnt[NFT];
// pair record: x = out position (b*K+i), y = down dict idx, z = up dict idx,
//              w = float bits of up_val[j]   (one record PER HIT, mult implicit)
__device__ uint4    g_bpairs[NFT * CAP];

// ---------------------------------------------------------------------------
// Kernel 1: bias = up_encoder_w @ b_dec. 2 rows/warp, 1536 blocks (full occ).
// Also zeroes the bucket counters.
// ---------------------------------------------------------------------------
__global__ __launch_bounds__(256) void bias_kernel(
    const float* __restrict__ up_encoder_w,   // [DICT, D]
    const float* __restrict__ b_dec)          // [D]
{
    int gid = blockIdx.x * 256 + threadIdx.x;
    if (gid < NFT) g_bcnt[gid] = 0;

    __shared__ float s_b[DDIM];
    for (int i = threadIdx.x; i < DDIM; i += blockDim.x) s_b[i] = b_dec[i];
    __syncthreads();

    int warp = threadIdx.x >> 5;
    int lane = threadIdx.x & 31;
    int row0 = (blockIdx.x * 8 + warp) * 2;      // 16 rows per block

    const float4* w  = reinterpret_cast<const float4*>(up_encoder_w + (size_t)row0 * DDIM);
    const float4* bb = reinterpret_cast<const float4*>(s_b);
    const int RS = DDIM / 4;                     // float4 row stride (192)
    float a0 = 0.f, a1 = 0.f;
#pragma unroll
    for (int k = 0; k < DDIM / 128; k++) {       // 6 iters, 12 indep loads
        int c = lane + 32 * k;
        float4 b  = bb[c];
        float4 v0 = w[c];
        float4 v1 = w[RS + c];
        a0 += v0.x * b.x + v0.y * b.y + v0.z * b.z + v0.w * b.w;
        a1 += v1.x * b.x + v1.y * b.y + v1.z * b.z + v1.w * b.w;
    }
#pragma unroll
    for (int o = 16; o > 0; o >>= 1) {
        a0 += __shfl_xor_sync(0xffffffffu, a0, o);
        a1 += __shfl_xor_sync(0xffffffffu, a1, o);
    }
    if (lane == 0) {
        g_bias[row0 + 0] = a0;
        g_bias[row0 + 1] = a1;
    }
}

// ---------------------------------------------------------------------------
// Kernel 2: matching via rare-hit bitmap. One block per batch element.
// Emits one pair record per matching (slot, j); writes bias base into out.
// ---------------------------------------------------------------------------
__global__ __launch_bounds__(128) void match_kernel(
    const float* __restrict__ up_vals,        // [B, K]
    const int*   __restrict__ up_indices,     // [B, K]
    const int*   __restrict__ down_indices,   // [B, K]
    const int*   __restrict__ connections,    // [DICT, C]
    float*       __restrict__ out)            // [B, K]
{
    __shared__ int      s_up_idx[KTOP];
    __shared__ float    s_up_val[KTOP];
    __shared__ int      s_down_idx[KTOP];
    __shared__ unsigned s_bm[DICT / 32];      // 768 words, 3KB presence bitmap

    const int b = blockIdx.x;
    const int t = threadIdx.x;

    // Zero bitmap: 6 words per thread.
#pragma unroll
    for (int r = 0; r < (DICT / 32) / 128; r++)
        s_bm[t + 128 * r] = 0u;

    if (t < KTOP) {
        int ui = up_indices[b * KTOP + t];
        s_up_idx[t]   = ui;
        s_up_val[t]   = up_vals[b * KTOP + t];
        s_down_idx[t] = down_indices[b * KTOP + t];
        out[b * KTOP + t] = g_bias[ui];       // bias base; dots add atomically
    }
    __syncthreads();

    if (t < KTOP)
        atomicOr(&s_bm[(unsigned)s_up_idx[t] >> 5], 1u << (s_up_idx[t] & 31));
    __syncthreads();

    // Stream connection slots through the bitmap: 32 rows x 16 int4 = 512 items.
#pragma unroll
    for (int item = t; item < KTOP * (CONN / 4); item += 128) {
        int i = item >> 4;
        int q = item & 15;
        int di = s_down_idx[i];
        int4 a = reinterpret_cast<const int4*>(connections + (size_t)di * CONN)[q];
        int av[4] = {a.x, a.y, a.z, a.w};
#pragma unroll
        for (int s = 0; s < 4; s++) {
            int v = av[s];
            bool hit = false;
            if (v >= 0)
                hit = (s_bm[(unsigned)v >> 5] >> (v & 31)) & 1u;
            if (hit) {
                // rare (~0.23% of slots): resolve which j's match (handles dups)
                for (int j = 0; j < KTOP; j++) {
                    if (s_up_idx[j] == v) {
                        unsigned pos = atomicAdd(&g_bcnt[(unsigned)v >> 6], 1u);
                        if (pos < CAP) {
                            uint4 rec;
                            rec.x = (unsigned)(b * KTOP + i);
                            rec.y = (unsigned)di;
                            rec.z = (unsigned)v;
                            rec.w = __float_as_uint(s_up_val[j]);
                            g_bpairs[((unsigned)v >> 6) * CAP + pos] = rec;
                        }
                    }
                }
            }
        }
    }
}

// ---------------------------------------------------------------------------
// Kernel 3: fused dot. One block per (f-tile, d-slice): load the 192x64 slab
// of up_decoder_w coalesced into smem, then each bucket record does a
// smem-column x down-row partial dot, atomicAdd into out.
// ---------------------------------------------------------------------------
__global__ __launch_bounds__(256) void fused_kernel(
    const float* __restrict__ up_decoder_w,   // [D, DICT]
    const float* __restrict__ down_encoder_w, // [DICT, D]
    float*       __restrict__ out)            // [B*K]
{
    extern __shared__ float s[];               // [DH][SROW]

    const int t = threadIdx.x;
    const int tile  = blockIdx.x >> 2;
    const int slice = blockIdx.x & 3;
    const unsigned cnt_raw = g_bcnt[tile];
    const int cnt = (int)(cnt_raw < CAP ? cnt_raw : CAP);
    if (cnt == 0) return;

    const int f0 = tile * FT;
    const int d0 = slice * DH;

    // Load slab: DH rows x FT cols = 3072 float4 / 256 threads = 12 each.
    const float4* src = reinterpret_cast<const float4*>(
        up_decoder_w + (size_t)d0 * DICT + f0);
    const int RS4 = DICT / 4;                  // float4 row stride
#pragma unroll
    for (int it = 0; it < (DH * FT / 4) / 256; it++) {
        int idx = t + 256 * it;
        int row = idx >> 4;                    // / (FT/4)
        int c4  = idx & 15;
        float4 v = src[(size_t)row * RS4 + c4];
        float* dst = &s[row * SROW + c4 * 4];
        dst[0] = v.x; dst[1] = v.y; dst[2] = v.z; dst[3] = v.w;
    }
    __syncthreads();

    const int warp = t >> 5;
    const int lane = t & 31;
    for (int p = warp; p < cnt; p += 8) {
        uint4 rec = g_bpairs[tile * CAP + p];
        const int fl = (int)rec.z - f0;
        const float* drow = down_encoder_w + (size_t)rec.y * DDIM + d0;
        float acc = 0.f;
#pragma unroll
        for (int m = 0; m < DH / 32; m++) {    // 6 iters
            int dd = lane + 32 * m;
            acc += s[dd * SROW + fl] * drow[dd];
        }
#pragma unroll
        for (int o = 16; o > 0; o >>= 1) acc += __shfl_xor_sync(0xffffffffu, acc, o);
        if (lane == 0)
            atomicAdd(&out[rec.x], acc * __uint_as_float(rec.w));
    }
}

// ---------------------------------------------------------------------------
extern "C" void kernel_launch(void* const* d_in, const int* in_sizes, int n_in,
                              void* d_out, int out_size)
{
    const float* up_vals        = (const float*)d_in[0];
    const float* up_decoder_w   = (const float*)d_in[1];
    const float* down_encoder_w = (const float*)d_in[2];
    const float* up_encoder_w   = (const float*)d_in[3];
    const float* b_dec          = (const float*)d_in[4];
    const int*   up_indices     = (const int*)d_in[5];
    const int*   down_indices   = (const int*)d_in[6];
    const int*   connections    = (const int*)d_in[7];
    float*       out            = (float*)d_out;

    const int smem = DH * SROW * sizeof(float);  // 49,920 B
    cudaFuncSetAttribute(fused_kernel,
                         cudaFuncAttributeMaxDynamicSharedMemorySize, smem);

    bias_kernel<<<DICT / 16, 256>>>(up_encoder_w, b_dec);
    match_kernel<<<BATCH, 128>>>(up_vals, up_indices, down_indices,
                                 connections, out);
    fused_kernel<<<NSL * NFT, 256, smem>>>(up_decoder_w, down_encoder_w, out);
}